// round 2
// baseline (speedup 1.0000x reference)
#include <cuda_runtime.h>

#define D_MODEL 256

// X kernel: out[stream][c][p], collapsed conv per stream.
__global__ __launch_bounds__(256) void embed_x_kernel(
    const float* __restrict__ x0, const float* __restrict__ x1,
    const float* __restrict__ x2,
    const float* __restrict__ W, const float* __restrict__ b,
    float* __restrict__ out, int l0, int l1, int l2, int ML)
{
    const int stream = blockIdx.z;
    const int c = blockIdx.y;
    const int p0 = (blockIdx.x * blockDim.x + threadIdx.x) * 4;
    if (p0 >= ML) return;

    const float bias = __ldg(&b[c]);
    const float* Wc = W + c * 5;
    float v[4];

    if (stream == 0) {
        const float w2 = __ldg(&Wc[2]);
        #pragma unroll
        for (int j = 0; j < 4; j++) {
            const int p = p0 + j;
            v[j] = (p < l0) ? fmaf(w2, __ldg(&x0[p]), bias) : 0.0f;
        }
    } else if (stream == 1) {
        const float w0 = __ldg(&Wc[0]);
        const float w2 = __ldg(&Wc[2]);
        const float w4 = __ldg(&Wc[4]);
        #pragma unroll
        for (int j = 0; j < 4; j++) {
            const int p = p0 + j;
            if (p < l1) {
                const float xm = (p >= 1)     ? __ldg(&x1[p - 1]) : 0.0f;
                const float xc =                __ldg(&x1[p]);
                const float xp = (p + 1 < l1) ? __ldg(&x1[p + 1]) : 0.0f;
                v[j] = fmaf(w0, xm, fmaf(w2, xc, fmaf(w4, xp, bias)));
            } else {
                v[j] = 0.0f;
            }
        }
    } else {
        const float w0 = __ldg(&Wc[0]);
        const float w1 = __ldg(&Wc[1]);
        const float w2 = __ldg(&Wc[2]);
        const float w3 = __ldg(&Wc[3]);
        const float w4 = __ldg(&Wc[4]);
        #pragma unroll
        for (int j = 0; j < 4; j++) {
            const int p = p0 + j;
            if (p < l2) {
                const float a0 = (p >= 2)     ? __ldg(&x2[p - 2]) : 0.0f;
                const float a1 = (p >= 1)     ? __ldg(&x2[p - 1]) : 0.0f;
                const float a2 =                __ldg(&x2[p]);
                const float a3 = (p + 1 < l2) ? __ldg(&x2[p + 1]) : 0.0f;
                const float a4 = (p + 2 < l2) ? __ldg(&x2[p + 2]) : 0.0f;
                v[j] = fmaf(w0, a0,
                       fmaf(w1, a1,
                       fmaf(w2, a2,
                       fmaf(w3, a3,
                       fmaf(w4, a4, bias)))));
            } else {
                v[j] = 0.0f;
            }
        }
    }

    float4* dst = reinterpret_cast<float4*>(
        out + ((size_t)stream * D_MODEL + c) * (size_t)ML + p0);
    *dst = make_float4(v[0], v[1], v[2], v[3]);
}

// S kernel: rows (first ML) then cols (next ML), int values stored as float.
__global__ __launch_bounds__(256) void embed_s_kernel(
    float* __restrict__ out_s, int l0, int l1, int l2, int ML)
{
    const int j = blockIdx.x * blockDim.x + threadIdx.x;
    if (j >= ML) return;
    int row, col;
    if (j < l0)            { row = 0; col = j * 4; }
    else if (j < l0 + l1)  { row = 1; col = (j - l0) * 2; }
    else if (j < l0 + l1 + l2) { row = 2; col = j - l0 - l1; }
    else                   { row = 0; col = 0; }
    out_s[j]      = (float)row;
    out_s[ML + j] = (float)col;
}

extern "C" void kernel_launch(void* const* d_in, const int* in_sizes, int n_in,
                              void* d_out, int out_size)
{
    const float* x0 = (const float*)d_in[0];  // x_250
    const float* x1 = (const float*)d_in[1];  // x_500
    const float* x2 = (const float*)d_in[2];  // x_1000
    const float* W  = (const float*)d_in[3];  // [256,1,5]
    const float* b  = (const float*)d_in[4];  // [256]

    const int l0 = in_sizes[0];
    const int l1 = in_sizes[1];
    const int l2 = in_sizes[2];
    int ML = l0;
    if (l1 > ML) ML = l1;
    if (l2 > ML) ML = l2;

    float* out = (float*)d_out;

    dim3 block(256, 1, 1);
    dim3 grid((ML / 4 + 255) / 256, D_MODEL, 3);
    embed_x_kernel<<<grid, block>>>(x0, x1, x2, W, b, out, l0, l1, l2, ML);

    const long long x_elems = 3LL * D_MODEL * (long long)ML;
    if ((long long)out_size >= x_elems + 2LL * ML) {
        embed_s_kernel<<<(ML + 255) / 256, 256>>>(out + x_elems, l0, l1, l2, ML);
    }
}

// round 3
// speedup vs baseline: 1.8759x; 1.8759x over previous
#include <cuda_runtime.h>

#define D_MODEL 256
#define CH_TILE 16
#define QUADS 4                         // position-quads per thread per channel
#define WARP_POS (32 * 4 * QUADS)       // 512 positions per warp
#define BLOCK_WARPS 8
#define BLOCK_POS (WARP_POS * BLOCK_WARPS)  // 4096 positions per block

// Collapsed conv per stream: zero-fill upsample + conv + strided gather reduces to
// a small FIR on the original samples (stream0: 1 tap, stream1: 3 taps, stream2: 5 taps).
template <int SID>
__device__ __forceinline__ void run_stream(
    const float* __restrict__ x, const float* __restrict__ W,
    const float* __restrict__ b, float* __restrict__ out,
    int l, int ML)
{
    const int warp = threadIdx.x >> 5;
    const int lane = threadIdx.x & 31;
    const int warpBase = blockIdx.x * BLOCK_POS + warp * WARP_POS;

    // Load input windows ONCE per thread; reused across the whole channel tile.
    // Window q covers x[pq-4 .. pq+7] (12 floats, 3 aligned float4s), zero-guarded.
    float xs[QUADS * 12];
    #pragma unroll
    for (int q = 0; q < QUADS; q++) {
        const int pq = warpBase + q * 128 + lane * 4;
        #pragma unroll
        for (int j = 0; j < 3; j++) {
            const int bb = pq - 4 + j * 4;
            float4 t;
            if (bb >= 0 && bb + 4 <= l) {
                t = *reinterpret_cast<const float4*>(x + bb);
            } else {
                t.x = (bb     >= 0 && bb     < l) ? x[bb]     : 0.0f;
                t.y = (bb + 1 >= 0 && bb + 1 < l) ? x[bb + 1] : 0.0f;
                t.z = (bb + 2 >= 0 && bb + 2 < l) ? x[bb + 2] : 0.0f;
                t.w = (bb + 3 >= 0 && bb + 3 < l) ? x[bb + 3] : 0.0f;
            }
            xs[q * 12 + j * 4 + 0] = t.x;
            xs[q * 12 + j * 4 + 1] = t.y;
            xs[q * 12 + j * 4 + 2] = t.z;
            xs[q * 12 + j * 4 + 3] = t.w;
        }
    }

    const int ch0 = blockIdx.y * CH_TILE;
    #pragma unroll 1
    for (int c = 0; c < CH_TILE; c++) {
        const int ch = ch0 + c;
        const float bias = __ldg(&b[ch]);
        const float* Wc = W + ch * 5;
        float w0 = 0.f, w1 = 0.f, w2, w3 = 0.f, w4 = 0.f;
        w2 = __ldg(&Wc[2]);
        if (SID >= 1) { w0 = __ldg(&Wc[0]); w4 = __ldg(&Wc[4]); }
        if (SID == 2) { w1 = __ldg(&Wc[1]); w3 = __ldg(&Wc[3]); }

        float* rowOut = out + ((size_t)(SID * D_MODEL + ch)) * (size_t)ML;

        #pragma unroll
        for (int q = 0; q < QUADS; q++) {
            const int pq = warpBase + q * 128 + lane * 4;
            if (pq >= ML) continue;

            float v[4];
            if (pq >= l) {
                v[0] = v[1] = v[2] = v[3] = 0.0f;
            } else {
                #pragma unroll
                for (int i = 0; i < 4; i++) {
                    // xs index: x[pq + k] == xs[q*12 + 4 + k]
                    float val;
                    if (SID == 0) {
                        val = fmaf(w2, xs[q * 12 + 4 + i], bias);
                    } else if (SID == 1) {
                        val = fmaf(w0, xs[q * 12 + 3 + i],
                              fmaf(w2, xs[q * 12 + 4 + i],
                              fmaf(w4, xs[q * 12 + 5 + i], bias)));
                    } else {
                        val = fmaf(w0, xs[q * 12 + 2 + i],
                              fmaf(w1, xs[q * 12 + 3 + i],
                              fmaf(w2, xs[q * 12 + 4 + i],
                              fmaf(w3, xs[q * 12 + 5 + i],
                              fmaf(w4, xs[q * 12 + 6 + i], bias)))));
                    }
                    v[i] = (pq + i < l) ? val : 0.0f;
                }
            }

            if (pq + 4 <= ML) {
                *reinterpret_cast<float4*>(rowOut + pq) =
                    make_float4(v[0], v[1], v[2], v[3]);
            } else {
                #pragma unroll
                for (int i = 0; i < 4; i++)
                    if (pq + i < ML) rowOut[pq + i] = v[i];
            }
        }
    }
}

__global__ __launch_bounds__(256) void embed_x_kernel(
    const float* __restrict__ x0, const float* __restrict__ x1,
    const float* __restrict__ x2,
    const float* __restrict__ W, const float* __restrict__ b,
    float* __restrict__ out, int l0, int l1, int l2, int ML)
{
    if (blockIdx.z == 0)      run_stream<0>(x0, W, b, out, l0, ML);
    else if (blockIdx.z == 1) run_stream<1>(x1, W, b, out, l1, ML);
    else                      run_stream<2>(x2, W, b, out, l2, ML);
}

// S matrix: rows (first ML) then cols (next ML), int values stored exactly as float.
__global__ __launch_bounds__(256) void embed_s_kernel(
    float* __restrict__ out_s, int l0, int l1, int l2, int ML)
{
    const int j = blockIdx.x * blockDim.x + threadIdx.x;
    if (j >= ML) return;
    int row, col;
    if (j < l0)                 { row = 0; col = j * 4; }
    else if (j < l0 + l1)       { row = 1; col = (j - l0) * 2; }
    else if (j < l0 + l1 + l2)  { row = 2; col = j - l0 - l1; }
    else                        { row = 0; col = 0; }
    out_s[j]      = (float)row;
    out_s[ML + j] = (float)col;
}

extern "C" void kernel_launch(void* const* d_in, const int* in_sizes, int n_in,
                              void* d_out, int out_size)
{
    const float* x0 = (const float*)d_in[0];  // x_250
    const float* x1 = (const float*)d_in[1];  // x_500
    const float* x2 = (const float*)d_in[2];  // x_1000
    const float* W  = (const float*)d_in[3];  // [256,1,5]
    const float* b  = (const float*)d_in[4];  // [256]

    const int l0 = in_sizes[0];
    const int l1 = in_sizes[1];
    const int l2 = in_sizes[2];
    int ML = l0;
    if (l1 > ML) ML = l1;
    if (l2 > ML) ML = l2;

    float* out = (float*)d_out;

    dim3 block(256, 1, 1);
    dim3 grid((ML + BLOCK_POS - 1) / BLOCK_POS, D_MODEL / CH_TILE, 3);
    embed_x_kernel<<<grid, block>>>(x0, x1, x2, W, b, out, l0, l1, l2, ML);

    const long long x_elems = 3LL * D_MODEL * (long long)ML;
    if ((long long)out_size >= x_elems + 2LL * ML) {
        embed_s_kernel<<<(ML + 255) / 256, 256>>>(out + x_elems, l0, l1, l2, ML);
    }
}

// round 4
// speedup vs baseline: 1.9019x; 1.0139x over previous
#include <cuda_runtime.h>

#define D_MODEL 256
#define CH_TILE 16
#define QUADS 4                         // position-quads per thread per channel
#define WARP_POS (32 * 4 * QUADS)       // 512 positions per warp
#define BLOCK_WARPS 8
#define BLOCK_POS (WARP_POS * BLOCK_WARPS)  // 4096 positions per block

// Collapsed conv per stream: zero-fill upsample + conv + strided gather reduces to
// a small FIR on the original samples (stream0: 1 tap, stream1: 3 taps, stream2: 5 taps).
template <int SID>
__device__ __forceinline__ void run_stream(
    const float* __restrict__ x, const float* __restrict__ W,
    const float* __restrict__ b, float* __restrict__ out,
    int l, int ML)
{
    const int warp = threadIdx.x >> 5;
    const int lane = threadIdx.x & 31;
    const int warpBase = blockIdx.x * BLOCK_POS + warp * WARP_POS;

    // Load input windows ONCE per thread; reused across the whole channel tile.
    // Window q covers x[pq-4 .. pq+7] (12 floats, 3 aligned float4s), zero-guarded.
    float xs[QUADS * 12];
    #pragma unroll
    for (int q = 0; q < QUADS; q++) {
        const int pq = warpBase + q * 128 + lane * 4;
        #pragma unroll
        for (int j = 0; j < 3; j++) {
            const int bb = pq - 4 + j * 4;
            float4 t;
            if (bb >= 0 && bb + 4 <= l) {
                t = *reinterpret_cast<const float4*>(x + bb);
            } else {
                t.x = (bb     >= 0 && bb     < l) ? x[bb]     : 0.0f;
                t.y = (bb + 1 >= 0 && bb + 1 < l) ? x[bb + 1] : 0.0f;
                t.z = (bb + 2 >= 0 && bb + 2 < l) ? x[bb + 2] : 0.0f;
                t.w = (bb + 3 >= 0 && bb + 3 < l) ? x[bb + 3] : 0.0f;
            }
            xs[q * 12 + j * 4 + 0] = t.x;
            xs[q * 12 + j * 4 + 1] = t.y;
            xs[q * 12 + j * 4 + 2] = t.z;
            xs[q * 12 + j * 4 + 3] = t.w;
        }
    }

    const int ch0 = blockIdx.y * CH_TILE;
    #pragma unroll 1
    for (int c = 0; c < CH_TILE; c++) {
        const int ch = ch0 + c;
        const float bias = __ldg(&b[ch]);
        const float* Wc = W + ch * 5;
        float w0 = 0.f, w1 = 0.f, w2, w3 = 0.f, w4 = 0.f;
        w2 = __ldg(&Wc[2]);
        if (SID >= 1) { w0 = __ldg(&Wc[0]); w4 = __ldg(&Wc[4]); }
        if (SID == 2) { w1 = __ldg(&Wc[1]); w3 = __ldg(&Wc[3]); }

        float* rowOut = out + ((size_t)(SID * D_MODEL + ch)) * (size_t)ML;

        #pragma unroll
        for (int q = 0; q < QUADS; q++) {
            const int pq = warpBase + q * 128 + lane * 4;
            if (pq >= ML) continue;

            float v[4];
            if (pq >= l) {
                v[0] = v[1] = v[2] = v[3] = 0.0f;
            } else {
                #pragma unroll
                for (int i = 0; i < 4; i++) {
                    // xs index: x[pq + k] == xs[q*12 + 4 + k]
                    float val;
                    if (SID == 0) {
                        val = fmaf(w2, xs[q * 12 + 4 + i], bias);
                    } else if (SID == 1) {
                        val = fmaf(w0, xs[q * 12 + 3 + i],
                              fmaf(w2, xs[q * 12 + 4 + i],
                              fmaf(w4, xs[q * 12 + 5 + i], bias)));
                    } else {
                        val = fmaf(w0, xs[q * 12 + 2 + i],
                              fmaf(w1, xs[q * 12 + 3 + i],
                              fmaf(w2, xs[q * 12 + 4 + i],
                              fmaf(w3, xs[q * 12 + 5 + i],
                              fmaf(w4, xs[q * 12 + 6 + i], bias)))));
                    }
                    v[i] = (pq + i < l) ? val : 0.0f;
                }
            }

            if (pq + 4 <= ML) {
                *reinterpret_cast<float4*>(rowOut + pq) =
                    make_float4(v[0], v[1], v[2], v[3]);
            } else {
                #pragma unroll
                for (int i = 0; i < 4; i++)
                    if (pq + i < ML) rowOut[pq + i] = v[i];
            }
        }
    }
}

__global__ __launch_bounds__(256) void embed_x_kernel(
    const float* __restrict__ x0, const float* __restrict__ x1,
    const float* __restrict__ x2,
    const float* __restrict__ W, const float* __restrict__ b,
    float* __restrict__ out, int l0, int l1, int l2, int ML, int emit_s)
{
    if (blockIdx.z == 0)      run_stream<0>(x0, W, b, out, l0, ML);
    else if (blockIdx.z == 1) run_stream<1>(x1, W, b, out, l1, ML);
    else                      run_stream<2>(x2, W, b, out, l2, ML);

    // Fused S matrix: rows (first ML) then cols (next ML), ints stored exactly
    // as floats. Handled by the (y==0, z==0) block slice for its position range.
    if (emit_s && blockIdx.y == 0 && blockIdx.z == 0) {
        float* out_s = out + 3LL * D_MODEL * (long long)ML;
        const int base = blockIdx.x * BLOCK_POS;
        #pragma unroll
        for (int k = 0; k < BLOCK_POS / 256; k++) {
            const int j = base + k * 256 + threadIdx.x;
            if (j >= ML) break;
            int row, col;
            if (j < l0)                 { row = 0; col = j * 4; }
            else if (j < l0 + l1)       { row = 1; col = (j - l0) * 2; }
            else if (j < l0 + l1 + l2)  { row = 2; col = j - l0 - l1; }
            else                        { row = 0; col = 0; }
            out_s[j]      = (float)row;
            out_s[ML + j] = (float)col;
        }
    }
}

extern "C" void kernel_launch(void* const* d_in, const int* in_sizes, int n_in,
                              void* d_out, int out_size)
{
    const float* x0 = (const float*)d_in[0];  // x_250
    const float* x1 = (const float*)d_in[1];  // x_500
    const float* x2 = (const float*)d_in[2];  // x_1000
    const float* W  = (const float*)d_in[3];  // [256,1,5]
    const float* b  = (const float*)d_in[4];  // [256]

    const int l0 = in_sizes[0];
    const int l1 = in_sizes[1];
    const int l2 = in_sizes[2];
    int ML = l0;
    if (l1 > ML) ML = l1;
    if (l2 > ML) ML = l2;

    float* out = (float*)d_out;

    const long long x_elems = 3LL * D_MODEL * (long long)ML;
    const int emit_s = ((long long)out_size >= x_elems + 2LL * ML) ? 1 : 0;

    dim3 block(256, 1, 1);
    dim3 grid((ML + BLOCK_POS - 1) / BLOCK_POS, D_MODEL / CH_TILE, 3);
    embed_x_kernel<<<grid, block>>>(x0, x1, x2, W, b, out, l0, l1, l2, ML, emit_s);
}

// round 6
// speedup vs baseline: 2.1088x; 1.1088x over previous
#include <cuda_runtime.h>

#define D_MODEL 256
#define CH_TILE 16
#define QUADS 4                         // position-quads per thread per channel
#define WARP_POS (32 * 4 * QUADS)       // 512 positions per warp
#define BLOCK_WARPS 8
#define BLOCK_POS (WARP_POS * BLOCK_WARPS)  // 4096 positions per block

// Collapsed conv per stream: zero-fill upsample + conv + strided gather reduces to
// a small FIR on the original samples (stream0: 1 tap, stream1: 3 taps, stream2: 5 taps).
template <int SID, bool GUARDED>
__device__ __forceinline__ void run_compute(
    const float* __restrict__ x, const float* __restrict__ W,
    const float* __restrict__ b, float* __restrict__ out,
    int l, int ML)
{
    const int warp = threadIdx.x >> 5;
    const int lane = threadIdx.x & 31;
    const int warpBase = blockIdx.x * BLOCK_POS + warp * WARP_POS;

    // Input windows loaded ONCE per thread; reused across the 16-channel tile.
    // Window q covers x[pq-4 .. pq+7] (12 floats, 3 float4s).
    float xs[QUADS * 12];
    #pragma unroll
    for (int q = 0; q < QUADS; q++) {
        const int pq = warpBase + q * 128 + lane * 4;
        #pragma unroll
        for (int j = 0; j < 3; j++) {
            const int bb = pq - 4 + j * 4;
            float4 t;
            if (!GUARDED) {
                t = *reinterpret_cast<const float4*>(x + bb);
            } else if (bb >= 0 && bb + 4 <= l) {
                t = *reinterpret_cast<const float4*>(x + bb);
            } else {
                t.x = (bb     >= 0 && bb     < l) ? x[bb]     : 0.0f;
                t.y = (bb + 1 >= 0 && bb + 1 < l) ? x[bb + 1] : 0.0f;
                t.z = (bb + 2 >= 0 && bb + 2 < l) ? x[bb + 2] : 0.0f;
                t.w = (bb + 3 >= 0 && bb + 3 < l) ? x[bb + 3] : 0.0f;
            }
            xs[q * 12 + j * 4 + 0] = t.x;
            xs[q * 12 + j * 4 + 1] = t.y;
            xs[q * 12 + j * 4 + 2] = t.z;
            xs[q * 12 + j * 4 + 3] = t.w;
        }
    }

    const int ch0 = blockIdx.y * CH_TILE;
    #pragma unroll 1
    for (int c = 0; c < CH_TILE; c++) {
        const int ch = ch0 + c;
        const float bias = __ldg(&b[ch]);
        const float* Wc = W + ch * 5;
        float w0 = 0.f, w1 = 0.f, w2, w3 = 0.f, w4 = 0.f;
        w2 = __ldg(&Wc[2]);
        if (SID >= 1) { w0 = __ldg(&Wc[0]); w4 = __ldg(&Wc[4]); }
        if (SID == 2) { w1 = __ldg(&Wc[1]); w3 = __ldg(&Wc[3]); }

        float* rowOut = out + ((size_t)(SID * D_MODEL + ch)) * (size_t)ML;

        #pragma unroll
        for (int q = 0; q < QUADS; q++) {
            const int pq = warpBase + q * 128 + lane * 4;
            if (GUARDED && pq >= ML) continue;

            float v[4];
            #pragma unroll
            for (int i = 0; i < 4; i++) {
                // xs index: x[pq + k] == xs[q*12 + 4 + k]
                float val;
                if (SID == 0) {
                    val = fmaf(w2, xs[q * 12 + 4 + i], bias);
                } else if (SID == 1) {
                    val = fmaf(w0, xs[q * 12 + 3 + i],
                          fmaf(w2, xs[q * 12 + 4 + i],
                          fmaf(w4, xs[q * 12 + 5 + i], bias)));
                } else {
                    val = fmaf(w0, xs[q * 12 + 2 + i],
                          fmaf(w1, xs[q * 12 + 3 + i],
                          fmaf(w2, xs[q * 12 + 4 + i],
                          fmaf(w3, xs[q * 12 + 5 + i],
                          fmaf(w4, xs[q * 12 + 6 + i], bias)))));
                }
                v[i] = (!GUARDED || (pq + i < l)) ? val : 0.0f;
            }

            // BLOCK_POS and ML are multiples of 4, so pq<ML implies pq+4<=ML.
            *reinterpret_cast<float4*>(rowOut + pq) =
                make_float4(v[0], v[1], v[2], v[3]);
        }
    }
}

template <int SID>
__device__ __forceinline__ void run_zero(float* __restrict__ out, int ML)
{
    const int warp = threadIdx.x >> 5;
    const int lane = threadIdx.x & 31;
    const int warpBase = blockIdx.x * BLOCK_POS + warp * WARP_POS;
    const int ch0 = blockIdx.y * CH_TILE;
    const float4 z4 = make_float4(0.f, 0.f, 0.f, 0.f);

    #pragma unroll 1
    for (int c = 0; c < CH_TILE; c++) {
        float* rowOut = out + ((size_t)(SID * D_MODEL + ch0 + c)) * (size_t)ML;
        #pragma unroll
        for (int q = 0; q < QUADS; q++) {
            const int pq = warpBase + q * 128 + lane * 4;
            if (pq < ML)
                *reinterpret_cast<float4*>(rowOut + pq) = z4;
        }
    }
}

template <int SID>
__device__ __forceinline__ void run_stream(
    const float* __restrict__ x, const float* __restrict__ W,
    const float* __restrict__ b, float* __restrict__ out,
    int l, int ML)
{
    const int base = blockIdx.x * BLOCK_POS;
    if (base >= l) {
        run_zero<SID>(out, ML);
    } else if (base >= 4 && base + BLOCK_POS + 8 <= l) {
        run_compute<SID, false>(x, W, b, out, l, ML);
    } else {
        run_compute<SID, true>(x, W, b, out, l, ML);
    }
}

__global__ __launch_bounds__(256) void embed_x_kernel(
    const float* __restrict__ x0, const float* __restrict__ x1,
    const float* __restrict__ x2,
    const float* __restrict__ W, const float* __restrict__ b,
    float* __restrict__ out, int l0, int l1, int l2, int ML, int emit_s)
{
    if (blockIdx.z == 0)      run_stream<0>(x0, W, b, out, l0, ML);
    else if (blockIdx.z == 1) run_stream<1>(x1, W, b, out, l1, ML);
    else                      run_stream<2>(x2, W, b, out, l2, ML);

    // Fused S matrix: rows (first ML) then cols (next ML), ints stored exactly
    // as floats. Handled by the (y==0, z==0) block slice for its position range.
    if (emit_s && blockIdx.y == 0 && blockIdx.z == 0) {
        float* out_s = out + 3LL * D_MODEL * (long long)ML;
        const int base = blockIdx.x * BLOCK_POS;
        #pragma unroll
        for (int k = 0; k < BLOCK_POS / 256; k++) {
            const int j = base + k * 256 + threadIdx.x;
            if (j >= ML) break;
            int row, col;
            if (j < l0)                 { row = 0; col = j * 4; }
            else if (j < l0 + l1)       { row = 1; col = (j - l0) * 2; }
            else if (j < l0 + l1 + l2)  { row = 2; col = j - l0 - l1; }
            else                        { row = 0; col = 0; }
            out_s[j]      = (float)row;
            out_s[ML + j] = (float)col;
        }
    }
}

extern "C" void kernel_launch(void* const* d_in, const int* in_sizes, int n_in,
                              void* d_out, int out_size)
{
    const float* x0 = (const float*)d_in[0];  // x_250
    const float* x1 = (const float*)d_in[1];  // x_500
    const float* x2 = (const float*)d_in[2];  // x_1000
    const float* W  = (const float*)d_in[3];  // [256,1,5]
    const float* b  = (const float*)d_in[4];  // [256]

    const int l0 = in_sizes[0];
    const int l1 = in_sizes[1];
    const int l2 = in_sizes[2];
    int ML = l0;
    if (l1 > ML) ML = l1;
    if (l2 > ML) ML = l2;

    float* out = (float*)d_out;

    const long long x_elems = 3LL * D_MODEL * (long long)ML;
    const int emit_s = ((long long)out_size >= x_elems + 2LL * ML) ? 1 : 0;

    dim3 block(256, 1, 1);
    dim3 grid((ML + BLOCK_POS - 1) / BLOCK_POS, D_MODEL / CH_TILE, 3);
    embed_x_kernel<<<grid, block>>>(x0, x1, x2, W, b, out, l0, l1, l2, ML, emit_s);
}